// round 7
// baseline (speedup 1.0000x reference)
#include <cuda_runtime.h>

// sim = dot(f, m[idx]) / ((||f||+eps) * (||m[idx]||+eps))
// out = sim>=0.6 ? 0 : sim>=0.4 ? 1 : 2
// Output buffer is FLOAT32 (bench pipeline materializes the int64 reference as
// float for comparison — integer writes read back as denormals ≈ 0, which is
// exactly the rel_err=1.0 signature seen in R4-R6).
// Dataset: N=100000, C=10000, D=768. Inputs identified BY SIZE (order-proof).

#define MAX_C 16384
#define WARPS_PER_BLOCK 8
#define THREADS (WARPS_PER_BLOCK * 32)

__device__ float d_mem_inv[MAX_C];  // 1/(||mem_row||+eps); allocation-free scratch

__global__ void mem_norm_kernel(const float* __restrict__ mem, int C, int D) {
    int row = blockIdx.x * WARPS_PER_BLOCK + (threadIdx.x >> 5);
    int lane = threadIdx.x & 31;
    if (row >= C) return;
    const float4* m = reinterpret_cast<const float4*>(mem + (size_t)row * D);
    int nvec = D >> 2;
    float s = 0.f;
    for (int j = lane; j < nvec; j += 32) {
        float4 v = m[j];
        s += v.x * v.x + v.y * v.y + v.z * v.z + v.w * v.w;
    }
    #pragma unroll
    for (int o = 16; o > 0; o >>= 1) s += __shfl_xor_sync(0xffffffffu, s, o);
    if (lane == 0) d_mem_inv[row] = 1.0f / (sqrtf(s) + 1e-12f);
}

__global__ void sim_bucket_kernel(const float* __restrict__ feats,
                                  const float* __restrict__ mem,
                                  const int* __restrict__ idx,
                                  float* __restrict__ out,
                                  int N, int C, int D) {
    int row = blockIdx.x * WARPS_PER_BLOCK + (threadIdx.x >> 5);
    int lane = threadIdx.x & 31;
    if (row >= N) return;

    int c = idx[row];
    c = min(max(c, 0), C - 1);        // clamp: wrong-answer beats illegal-access
    const float4* f = reinterpret_cast<const float4*>(feats + (size_t)row * D);
    const float4* m = reinterpret_cast<const float4*>(mem + (size_t)c * D);

    int nvec = D >> 2;  // 192 for D=768 -> 6 iters, coalesced 512B warp transactions
    float dot = 0.f, nf = 0.f;
    #pragma unroll 6
    for (int j = lane; j < nvec; j += 32) {
        float4 a = f[j];
        float4 b = __ldg(&m[j]);
        dot += a.x * b.x + a.y * b.y + a.z * b.z + a.w * b.w;
        nf  += a.x * a.x + a.y * a.y + a.z * a.z + a.w * a.w;
    }
    #pragma unroll
    for (int o = 16; o > 0; o >>= 1) {
        dot += __shfl_xor_sync(0xffffffffu, dot, o);
        nf  += __shfl_xor_sync(0xffffffffu, nf, o);
    }
    if (lane == 0) {
        float inv_f = 1.0f / (sqrtf(nf) + 1e-12f);
        float sim = dot * inv_f * d_mem_inv[c];
        out[row] = (sim >= 0.6f) ? 0.0f : ((sim >= 0.4f) ? 1.0f : 2.0f);
    }
}

extern "C" void kernel_launch(void* const* d_in, const int* in_sizes, int n_in,
                              void* d_out, int out_size) {
    // Identify inputs purely by element count — robust to ANY ordering:
    //   idx   = smallest (N = 1e5 elements)
    //   feats = largest  (N*D = 7.68e7)
    //   memory= middle   (C*D = 7.68e6)
    int pi = 0, pf = 0;
    for (int i = 1; i < 3; i++) {
        if (in_sizes[i] < in_sizes[pi]) pi = i;   // smallest -> idx
        if (in_sizes[i] > in_sizes[pf]) pf = i;   // largest  -> feats
    }
    int pm = 3 - pi - pf;                          // remaining -> memory

    const int*   idx   = (const int*)d_in[pi];
    const float* feats = (const float*)d_in[pf];
    const float* mem   = (const float*)d_in[pm];

    int N = in_sizes[pi];                 // 100000 (element count of mem_idx)
    int D = in_sizes[pf] / N;             // 768
    int C = in_sizes[pm] / D;             // 10000
    if (C > MAX_C) C = MAX_C;

    float* out = (float*)d_out;           // [N] float32 (see header comment)

    int grid1 = (C + WARPS_PER_BLOCK - 1) / WARPS_PER_BLOCK;
    mem_norm_kernel<<<grid1, THREADS>>>(mem, C, D);

    int grid2 = (N + WARPS_PER_BLOCK - 1) / WARPS_PER_BLOCK;
    sim_bucket_kernel<<<grid2, THREADS>>>(feats, mem, idx, out, N, C, D);
}

// round 8
// speedup vs baseline: 1.2666x; 1.2666x over previous
#include <cuda_runtime.h>

// sim = dot(f, m[idx]) / ((||f||+eps)*(||m[idx]||+eps)); bucket 0/1/2 -> float32 out.
// Dataset: N=100000, C=10000, D=768. Inputs identified BY SIZE (order-proof).
// Single fused kernel: warp-per-row, all 12 float4 loads front-batched (MLP~12),
// mem-norm computed inline from the already-loaded registers (saves the 30MB
// precompute re-read), feats loaded evict-first (__ldcs) to keep memory in L2.

#define WPB 8
#define THREADS (WPB * 32)

__global__ __launch_bounds__(THREADS)
void sim_bucket_fused(const float* __restrict__ feats,
                      const float* __restrict__ mem,
                      const int* __restrict__ idx,
                      float* __restrict__ out,
                      int N, int C) {
    int row = blockIdx.x * WPB + (threadIdx.x >> 5);
    int lane = threadIdx.x & 31;
    if (row >= N) return;

    int c = idx[row];                   // warp-uniform broadcast load
    c = min(max(c, 0), C - 1);          // clamp: wrong-answer beats illegal-access

    const float4* f = reinterpret_cast<const float4*>(feats) + (size_t)row * 192 + lane;
    const float4* m = reinterpret_cast<const float4*>(mem)   + (size_t)c   * 192 + lane;

    // Front-batch ALL loads: 6 feats (DRAM, streaming) + 6 mem (L2-resident).
    float4 a0 = __ldcs(f);        float4 a1 = __ldcs(f + 32);
    float4 a2 = __ldcs(f + 64);   float4 a3 = __ldcs(f + 96);
    float4 a4 = __ldcs(f + 128);  float4 a5 = __ldcs(f + 160);
    float4 b0 = __ldg(m);         float4 b1 = __ldg(m + 32);
    float4 b2 = __ldg(m + 64);    float4 b3 = __ldg(m + 96);
    float4 b4 = __ldg(m + 128);   float4 b5 = __ldg(m + 160);

    float dot = 0.f, nf = 0.f, nm = 0.f;
    #define ACC(a, b)                                                \
        dot += a.x*b.x + a.y*b.y + a.z*b.z + a.w*b.w;                \
        nf  += a.x*a.x + a.y*a.y + a.z*a.z + a.w*a.w;                \
        nm  += b.x*b.x + b.y*b.y + b.z*b.z + b.w*b.w;
    ACC(a0, b0) ACC(a1, b1) ACC(a2, b2) ACC(a3, b3) ACC(a4, b4) ACC(a5, b5)
    #undef ACC

    #pragma unroll
    for (int o = 16; o > 0; o >>= 1) {
        dot += __shfl_xor_sync(0xffffffffu, dot, o);
        nf  += __shfl_xor_sync(0xffffffffu, nf, o);
        nm  += __shfl_xor_sync(0xffffffffu, nm, o);
    }
    if (lane == 0) {
        float sim = dot / ((sqrtf(nf) + 1e-12f) * (sqrtf(nm) + 1e-12f));
        out[row] = (sim >= 0.6f) ? 0.0f : ((sim >= 0.4f) ? 1.0f : 2.0f);
    }
}

// Generic fallback (any D multiple of 4) — only used if D != 768.
__global__ void sim_bucket_generic(const float* __restrict__ feats,
                                   const float* __restrict__ mem,
                                   const int* __restrict__ idx,
                                   float* __restrict__ out,
                                   int N, int C, int D) {
    int row = blockIdx.x * WPB + (threadIdx.x >> 5);
    int lane = threadIdx.x & 31;
    if (row >= N) return;
    int c = idx[row];
    c = min(max(c, 0), C - 1);
    const float4* f = reinterpret_cast<const float4*>(feats + (size_t)row * D);
    const float4* m = reinterpret_cast<const float4*>(mem + (size_t)c * D);
    int nvec = D >> 2;
    float dot = 0.f, nf = 0.f, nm = 0.f;
    for (int j = lane; j < nvec; j += 32) {
        float4 a = f[j], b = __ldg(&m[j]);
        dot += a.x*b.x + a.y*b.y + a.z*b.z + a.w*b.w;
        nf  += a.x*a.x + a.y*a.y + a.z*a.z + a.w*a.w;
        nm  += b.x*b.x + b.y*b.y + b.z*b.z + b.w*b.w;
    }
    #pragma unroll
    for (int o = 16; o > 0; o >>= 1) {
        dot += __shfl_xor_sync(0xffffffffu, dot, o);
        nf  += __shfl_xor_sync(0xffffffffu, nf, o);
        nm  += __shfl_xor_sync(0xffffffffu, nm, o);
    }
    if (lane == 0) {
        float sim = dot / ((sqrtf(nf) + 1e-12f) * (sqrtf(nm) + 1e-12f));
        out[row] = (sim >= 0.6f) ? 0.0f : ((sim >= 0.4f) ? 1.0f : 2.0f);
    }
}

extern "C" void kernel_launch(void* const* d_in, const int* in_sizes, int n_in,
                              void* d_out, int out_size) {
    // Identify inputs purely by element count (robust to any ordering):
    //   idx = smallest, feats = largest, memory = middle.
    int pi = 0, pf = 0;
    for (int i = 1; i < 3; i++) {
        if (in_sizes[i] < in_sizes[pi]) pi = i;
        if (in_sizes[i] > in_sizes[pf]) pf = i;
    }
    int pm = 3 - pi - pf;

    const int*   idx   = (const int*)d_in[pi];
    const float* feats = (const float*)d_in[pf];
    const float* mem   = (const float*)d_in[pm];

    int N = in_sizes[pi];        // 100000
    int D = in_sizes[pf] / N;    // 768
    int C = in_sizes[pm] / D;    // 10000

    float* out = (float*)d_out;  // [N] float32

    int grid = (N + WPB - 1) / WPB;
    if (D == 768) {
        sim_bucket_fused<<<grid, THREADS>>>(feats, mem, idx, out, N, C);
    } else {
        sim_bucket_generic<<<grid, THREADS>>>(feats, mem, idx, out, N, C, D);
    }
}